// round 1
// baseline (speedup 1.0000x reference)
#include <cuda_runtime.h>

// Problem constants
#define S_LEN   2048
#define D_MODEL 768
#define N_HEAD  12
#define DK      64
#define BATCH   2
#define NTOK    (BATCH * S_LEN)      // 4096
#define QKV_COLS (3 * D_MODEL)       // 2304

// Scratch (allocation-free rule: __device__ globals)
__device__ float g_qkv[NTOK * QKV_COLS];    // [4096, 2304]
__device__ float g_attn[NTOK * D_MODEL];    // [4096, 768]
__device__ unsigned char g_mask[NTOK];      // canonical 0/1 bytes

// ---------------------------------------------------------------------------
// Mask canonicalization: the harness may deliver the bool mask as 1-byte
// (bool/int8) or 4-byte (int32/float32). Detect from byte layout:
// for 4-byte 0/1 (int32 "01 00 00 00", float 1.0f "00 00 80 3F"), every byte
// at offset i%4==1 is zero. A random 1-byte mask has ~half of those nonzero.
// ---------------------------------------------------------------------------
__global__ void prep_mask_kernel(const unsigned char* __restrict__ m) {
    __shared__ int flags[2];  // [0]=has_any_nonzero, [1]=has_byte1_nonzero
    if (threadIdx.x < 2) flags[threadIdx.x] = 0;
    __syncthreads();
    for (int i = threadIdx.x; i < NTOK; i += blockDim.x) {
        unsigned char v = m[i];
        if (v) {
            atomicOr(&flags[0], 1);
            if ((i & 3) == 1) atomicOr(&flags[1], 1);
        }
    }
    __syncthreads();
    int has_any = flags[0], one_byte = flags[1];
    for (int i = threadIdx.x; i < NTOK; i += blockDim.x) {
        unsigned char v;
        if (!has_any)       v = 0;                       // all-false: no OOB reads
        else if (one_byte)  v = m[i] ? 1 : 0;            // 1-byte layout
        else                v = (m[4*i] | m[4*i+1] | m[4*i+2] | m[4*i+3]) ? 1 : 0; // 4-byte
        g_mask[i] = v;
    }
}

// ---------------------------------------------------------------------------
// SGEMM with bias: C[M,N] = A[M,K] @ B[K,N] + bias[N]
// 128x128 block tile, BK=16, 256 threads, 8x8 per-thread microtile.
// M,N,K all multiples of tile dims for our shapes (no bounds checks).
// ---------------------------------------------------------------------------
template <int BK>
__global__ void __launch_bounds__(256)
sgemm_bias_kernel(const float* __restrict__ A, const float* __restrict__ B,
                  const float* __restrict__ bias, float* __restrict__ C,
                  int M, int N, int K)
{
    __shared__ float As[BK][128];  // stored transposed: As[k][m]
    __shared__ float Bs[BK][128];

    const int tid = threadIdx.x;
    const int rowBase = blockIdx.y * 128;
    const int colBase = blockIdx.x * 128;
    const int row0 = (tid >> 4) * 8;
    const int col0 = (tid & 15) * 8;

    float acc[8][8] = {};

    for (int k0 = 0; k0 < K; k0 += BK) {
        // Load A tile: 128 rows x BK cols, transpose into As[k][m]
        #pragma unroll
        for (int i = 0; i < (128 * BK) / (256 * 4); i++) {
            int f  = tid + i * 256;
            int ar = f / (BK / 4);
            int ac = (f % (BK / 4)) * 4;
            float4 v = *(const float4*)&A[(size_t)(rowBase + ar) * K + k0 + ac];
            As[ac + 0][ar] = v.x; As[ac + 1][ar] = v.y;
            As[ac + 2][ar] = v.z; As[ac + 3][ar] = v.w;
        }
        // Load B tile: BK rows x 128 cols, direct
        #pragma unroll
        for (int i = 0; i < (128 * BK) / (256 * 4); i++) {
            int f  = tid + i * 256;
            int br = f / 32;
            int bc = (f & 31) * 4;
            *(float4*)&Bs[br][bc] =
                *(const float4*)&B[(size_t)(k0 + br) * N + colBase + bc];
        }
        __syncthreads();

        #pragma unroll
        for (int kk = 0; kk < BK; kk++) {
            float a[8], b[8];
            *(float4*)&a[0] = *(float4*)&As[kk][row0];
            *(float4*)&a[4] = *(float4*)&As[kk][row0 + 4];
            *(float4*)&b[0] = *(float4*)&Bs[kk][col0];
            *(float4*)&b[4] = *(float4*)&Bs[kk][col0 + 4];
            #pragma unroll
            for (int i = 0; i < 8; i++)
                #pragma unroll
                for (int j = 0; j < 8; j++)
                    acc[i][j] += a[i] * b[j];
        }
        __syncthreads();
    }

    #pragma unroll
    for (int i = 0; i < 8; i++) {
        int gr = rowBase + row0 + i;
        #pragma unroll
        for (int j = 0; j < 8; j += 4) {
            int gc = colBase + col0 + j;
            float4 o;
            o.x = acc[i][j + 0] + bias[gc + 0];
            o.y = acc[i][j + 1] + bias[gc + 1];
            o.z = acc[i][j + 2] + bias[gc + 2];
            o.w = acc[i][j + 3] + bias[gc + 3];
            *(float4*)&C[(size_t)gr * N + gc] = o;
        }
    }
}

// ---------------------------------------------------------------------------
// Flash-style masked attention.
// Grid: (S/128, N_HEAD, BATCH), 256 threads.
// BQ=128 query rows per block, BKT=128 keys per tile, dk=64.
// Smem (dynamic, 160KB): Qt[64][128] (d-major), Kt[64][128], Vs[128][64],
//                        Pt[128][128] (key-major P for the PV GEMM).
// Softmax stats (m,l) live in registers, reduced across the 16-thread column
// groups with shfl_xor (width 16 within each half-warp).
// ---------------------------------------------------------------------------
#define BQ  128
#define BKT 128

__global__ void __launch_bounds__(256) attention_kernel()
{
    extern __shared__ float sm[];
    float* Qt = sm;                    // [64][128]
    float* Kt = sm + 64 * 128;         // [64][128]
    float* Vs = Kt + 64 * 128;         // [128][64]
    float* Pt = Vs + 128 * 64;         // [128][128]

    const int tid   = threadIdx.x;
    const int qtile = blockIdx.x;
    const int h     = blockIdx.y;
    const int b     = blockIdx.z;
    const int qbase = qtile * BQ;
    const int nbase = b * S_LEN;

    // Load Q tile transposed: Qt[d][q]
    #pragma unroll
    for (int i = 0; i < 8; i++) {
        int f  = tid + i * 256;
        int r  = f >> 4;          // query row 0..127
        int d4 = (f & 15) * 4;
        float4 v = *(const float4*)
            &g_qkv[(size_t)(nbase + qbase + r) * QKV_COLS + h * DK + d4];
        Qt[(d4 + 0) * 128 + r] = v.x;
        Qt[(d4 + 1) * 128 + r] = v.y;
        Qt[(d4 + 2) * 128 + r] = v.z;
        Qt[(d4 + 3) * 128 + r] = v.w;
    }

    const int ty = tid >> 4, tx = tid & 15;
    const int row0  = ty * 8;   // query rows owned by this thread
    const int col0s = tx * 8;   // key columns (scores microtile)
    const int col0v = tx * 4;   // dk columns (output microtile)

    float o[8][4] = {};
    float mrow[8], lrow[8];
    #pragma unroll
    for (int i = 0; i < 8; i++) { mrow[i] = -1e30f; lrow[i] = 0.f; }

    unsigned char qm[8];
    #pragma unroll
    for (int i = 0; i < 8; i++) qm[i] = g_mask[nbase + qbase + row0 + i];

    const float NEG = -1e9f, SCALE = 0.125f;  // 1/sqrt(64)

    for (int kt = 0; kt < S_LEN; kt += BKT) {
        __syncthreads();  // previous iteration's PV reads of Kt/Vs/Pt are done

        // Load K tile transposed (Kt[d][k]) and V tile natural (Vs[k][d])
        #pragma unroll
        for (int i = 0; i < 8; i++) {
            int f  = tid + i * 256;
            int r  = f >> 4;
            int d4 = (f & 15) * 4;
            size_t rowoff = (size_t)(nbase + kt + r) * QKV_COLS + h * DK + d4;
            float4 kv = *(const float4*)&g_qkv[rowoff + D_MODEL];
            Kt[(d4 + 0) * 128 + r] = kv.x;
            Kt[(d4 + 1) * 128 + r] = kv.y;
            Kt[(d4 + 2) * 128 + r] = kv.z;
            Kt[(d4 + 3) * 128 + r] = kv.w;
            float4 vv = *(const float4*)&g_qkv[rowoff + 2 * D_MODEL];
            *(float4*)&Vs[r * 64 + d4] = vv;
        }
        __syncthreads();

        // Scores: s[8][8] = Q[row0..+8] . K[col0s..+8]
        float s[8][8] = {};
        #pragma unroll 4
        for (int d = 0; d < 64; d++) {
            float a[8], bb[8];
            *(float4*)&a[0]  = *(float4*)&Qt[d * 128 + row0];
            *(float4*)&a[4]  = *(float4*)&Qt[d * 128 + row0 + 4];
            *(float4*)&bb[0] = *(float4*)&Kt[d * 128 + col0s];
            *(float4*)&bb[4] = *(float4*)&Kt[d * 128 + col0s + 4];
            #pragma unroll
            for (int i = 0; i < 8; i++)
                #pragma unroll
                for (int j = 0; j < 8; j++)
                    s[i][j] += a[i] * bb[j];
        }

        // Scale + mask
        unsigned char km[8];
        #pragma unroll
        for (int j = 0; j < 8; j++) km[j] = g_mask[nbase + kt + col0s + j];
        #pragma unroll
        for (int i = 0; i < 8; i++)
            #pragma unroll
            for (int j = 0; j < 8; j++) {
                float v = s[i][j] * SCALE;
                if (km[j] || qm[i]) v = NEG;
                s[i][j] = v;
            }

        // Online softmax per row (reduce across the 16 tx threads)
        #pragma unroll
        for (int i = 0; i < 8; i++) {
            float mx = s[i][0];
            #pragma unroll
            for (int j = 1; j < 8; j++) mx = fmaxf(mx, s[i][j]);
            #pragma unroll
            for (int off = 8; off >= 1; off >>= 1)
                mx = fmaxf(mx, __shfl_xor_sync(0xffffffffu, mx, off));
            float mnew  = fmaxf(mrow[i], mx);
            float alpha = __expf(mrow[i] - mnew);
            float sum = 0.f;
            #pragma unroll
            for (int j = 0; j < 8; j++) {
                float p = __expf(s[i][j] - mnew);
                s[i][j] = p;
                sum += p;
            }
            #pragma unroll
            for (int off = 8; off >= 1; off >>= 1)
                sum += __shfl_xor_sync(0xffffffffu, sum, off);
            lrow[i] = lrow[i] * alpha + sum;
            mrow[i] = mnew;
            #pragma unroll
            for (int j = 0; j < 4; j++) o[i][j] *= alpha;
        }

        // Write P transposed: Pt[key][query]
        #pragma unroll
        for (int i = 0; i < 8; i++)
            #pragma unroll
            for (int j = 0; j < 8; j++)
                Pt[(col0s + j) * 128 + (row0 + i)] = s[i][j];
        __syncthreads();

        // PV: o[i][jj] += sum_k P[row][k] * V[k][col]
        #pragma unroll 2
        for (int k = 0; k < BKT; k++) {
            float p[8];
            *(float4*)&p[0] = *(float4*)&Pt[k * 128 + row0];
            *(float4*)&p[4] = *(float4*)&Pt[k * 128 + row0 + 4];
            float4 vv = *(float4*)&Vs[k * 64 + col0v];
            #pragma unroll
            for (int i = 0; i < 8; i++) {
                o[i][0] += p[i] * vv.x;
                o[i][1] += p[i] * vv.y;
                o[i][2] += p[i] * vv.z;
                o[i][3] += p[i] * vv.w;
            }
        }
    }

    // Normalize and write out in [B, S, H*dk] layout (== transpose(0,2,1,3))
    #pragma unroll
    for (int i = 0; i < 8; i++) {
        float inv = 1.0f / lrow[i];
        float4 v;
        v.x = o[i][0] * inv; v.y = o[i][1] * inv;
        v.z = o[i][2] * inv; v.w = o[i][3] * inv;
        *(float4*)&g_attn[(size_t)(nbase + qbase + row0 + i) * D_MODEL
                          + h * DK + col0v] = v;
    }
}

// ---------------------------------------------------------------------------
// Launch
// ---------------------------------------------------------------------------
extern "C" void kernel_launch(void* const* d_in, const int* in_sizes, int n_in,
                              void* d_out, int out_size)
{
    const float*         x    = (const float*)d_in[0];
    const unsigned char* mask = (const unsigned char*)d_in[1];
    const float*         Wqkv = (const float*)d_in[2];
    const float*         bqkv = (const float*)d_in[3];
    const float*         Wout = (const float*)d_in[4];
    const float*         bout = (const float*)d_in[5];
    float*               out  = (float*)d_out;

    // 160KB dynamic smem for the attention kernel (not a stream op; capture-safe)
    cudaFuncSetAttribute(attention_kernel,
                         cudaFuncAttributeMaxDynamicSharedMemorySize, 164 * 1024);

    void* qkv_ptr  = nullptr;
    void* attn_ptr = nullptr;
    cudaGetSymbolAddress(&qkv_ptr, g_qkv);
    cudaGetSymbolAddress(&attn_ptr, g_attn);

    prep_mask_kernel<<<1, 256>>>(mask);

    // QKV projection: [4096,768] @ [768,2304] + bias
    sgemm_bias_kernel<16><<<dim3(QKV_COLS / 128, NTOK / 128), 256>>>(
        x, Wqkv, bqkv, (float*)qkv_ptr, NTOK, QKV_COLS, D_MODEL);

    // Masked multi-head attention
    attention_kernel<<<dim3(S_LEN / BQ, N_HEAD, BATCH), 256, 160 * 1024>>>();

    // Output projection: [4096,768] @ [768,768] + bias
    sgemm_bias_kernel<16><<<dim3(D_MODEL / 128, NTOK / 128), 256>>>(
        (const float*)attn_ptr, Wout, bout, out, NTOK, D_MODEL, D_MODEL);
}

// round 3
// speedup vs baseline: 2.9725x; 2.9725x over previous
#include <cuda_runtime.h>
#include <cstdint>

#define S_LEN   2048
#define D_MODEL 768
#define N_HEAD  12
#define DK      64
#define BATCH   2
#define NTOK    4096
#define QKV_COLS 2304

__device__ float g_qkv[NTOK * QKV_COLS];
__device__ float g_attn[NTOK * D_MODEL];
__device__ unsigned char g_mask[NTOK];

// ---------------------------------------------------------------------------
// helpers
// ---------------------------------------------------------------------------
__device__ __forceinline__ uint32_t f2tf(float f) {
    uint32_t u;
    asm("cvt.rna.tf32.f32 %0, %1;" : "=r"(u) : "f"(f));
    return u;
}

__device__ __forceinline__ void mma8(float* c, const uint32_t* a, const uint32_t* b) {
    asm("mma.sync.aligned.m16n8k8.row.col.f32.tf32.tf32.f32 "
        "{%0,%1,%2,%3}, {%4,%5,%6,%7}, {%8,%9}, {%0,%1,%2,%3};"
        : "+f"(c[0]), "+f"(c[1]), "+f"(c[2]), "+f"(c[3])
        : "r"(a[0]), "r"(a[1]), "r"(a[2]), "r"(a[3]), "r"(b[0]), "r"(b[1]));
}

// ---------------------------------------------------------------------------
// Mask canonicalization (1-byte vs 4-byte bool layouts)
// ---------------------------------------------------------------------------
__global__ void prep_mask_kernel(const unsigned char* __restrict__ m) {
    __shared__ int flags[2];
    if (threadIdx.x < 2) flags[threadIdx.x] = 0;
    __syncthreads();
    for (int i = threadIdx.x; i < NTOK; i += blockDim.x) {
        unsigned char v = m[i];
        if (v) {
            atomicOr(&flags[0], 1);
            if ((i & 3) == 1) atomicOr(&flags[1], 1);
        }
    }
    __syncthreads();
    int has_any = flags[0], one_byte = flags[1];
    for (int i = threadIdx.x; i < NTOK; i += blockDim.x) {
        unsigned char v;
        if (!has_any)      v = 0;
        else if (one_byte) v = m[i] ? 1 : 0;
        else               v = (m[4*i] | m[4*i+1] | m[4*i+2] | m[4*i+3]) ? 1 : 0;
        g_mask[i] = v;
    }
}

// ---------------------------------------------------------------------------
// TF32 GEMM with bias: C[M,N] = A[M,K] @ B[K,N] + bias
// 128x128x32 tiles, 256 threads (8 warps, 4x2), warp tile 32x64, m16n8k8 mma.
// Double-buffered smem. A stride 36, B stride 136 -> conflict-free frag loads.
// ---------------------------------------------------------------------------
#define GBK 32
#define ASTRIDE 36
#define BSTRIDE 136
#define AWORDS (128 * ASTRIDE)
#define BWORDS (GBK * BSTRIDE)
#define GEMM_SMEM_BYTES (2 * (AWORDS + BWORDS) * 4)

__global__ void __launch_bounds__(256, 1)
gemm_tf32_bias(const float* __restrict__ A, const float* __restrict__ B,
               const float* __restrict__ bias, float* __restrict__ C,
               int M, int N, int K)
{
    extern __shared__ uint32_t sh[];
    uint32_t* As = sh;
    uint32_t* Bs = sh + 2 * AWORDS;

    const int tid = threadIdx.x;
    const int lane = tid & 31, wid = tid >> 5;
    const int lq = lane >> 2, lr = lane & 3;
    const int warpM = wid >> 1, warpN = wid & 1;
    const int rowBase = blockIdx.y * 128, colBase = blockIdx.x * 128;

    const int arow = tid >> 3, acol = (tid & 7) << 2;   // +p*32 rows
    const int brow = tid >> 5, bcol = (tid & 31) << 2;  // +p*8 rows

    float acc[2][8][4] = {};

    // prologue: tile 0
    #pragma unroll
    for (int p = 0; p < 4; p++) {
        float4 va = *(const float4*)&A[(size_t)(rowBase + p*32 + arow) * K + acol];
        uint4 ua = { f2tf(va.x), f2tf(va.y), f2tf(va.z), f2tf(va.w) };
        *(uint4*)&As[(p*32 + arow) * ASTRIDE + acol] = ua;
        float4 vb = *(const float4*)&B[(size_t)(p*8 + brow) * N + colBase + bcol];
        uint4 ub = { f2tf(vb.x), f2tf(vb.y), f2tf(vb.z), f2tf(vb.w) };
        *(uint4*)&Bs[(p*8 + brow) * BSTRIDE + bcol] = ub;
    }
    __syncthreads();

    const int T = K / GBK;
    for (int t = 0; t < T; t++) {
        const uint32_t* Ab = As + (t & 1) * AWORDS;
        const uint32_t* Bb = Bs + (t & 1) * BWORDS;

        float4 pfA[4], pfB[4];
        if (t + 1 < T) {
            int k0 = (t + 1) * GBK;
            #pragma unroll
            for (int p = 0; p < 4; p++) {
                pfA[p] = *(const float4*)&A[(size_t)(rowBase + p*32 + arow) * K + k0 + acol];
                pfB[p] = *(const float4*)&B[(size_t)(k0 + p*8 + brow) * N + colBase + bcol];
            }
        }

        #pragma unroll
        for (int ks = 0; ks < 4; ks++) {
            const int k = ks * 8;
            uint32_t af[2][4], bf[8][2];
            #pragma unroll
            for (int mt = 0; mt < 2; mt++) {
                int r = warpM * 32 + mt * 16 + lq;
                af[mt][0] = Ab[r * ASTRIDE + k + lr];
                af[mt][1] = Ab[(r + 8) * ASTRIDE + k + lr];
                af[mt][2] = Ab[r * ASTRIDE + k + lr + 4];
                af[mt][3] = Ab[(r + 8) * ASTRIDE + k + lr + 4];
            }
            #pragma unroll
            for (int nt = 0; nt < 8; nt++) {
                int n = warpN * 64 + nt * 8 + lq;
                bf[nt][0] = Bb[(k + lr) * BSTRIDE + n];
                bf[nt][1] = Bb[(k + lr + 4) * BSTRIDE + n];
            }
            #pragma unroll
            for (int mt = 0; mt < 2; mt++)
                #pragma unroll
                for (int nt = 0; nt < 8; nt++)
                    mma8(acc[mt][nt], af[mt], bf[nt]);
        }

        if (t + 1 < T) {
            uint32_t* An = As + ((t + 1) & 1) * AWORDS;
            uint32_t* Bn = Bs + ((t + 1) & 1) * BWORDS;
            #pragma unroll
            for (int p = 0; p < 4; p++) {
                uint4 ua = { f2tf(pfA[p].x), f2tf(pfA[p].y), f2tf(pfA[p].z), f2tf(pfA[p].w) };
                *(uint4*)&An[(p*32 + arow) * ASTRIDE + acol] = ua;
                uint4 ub = { f2tf(pfB[p].x), f2tf(pfB[p].y), f2tf(pfB[p].z), f2tf(pfB[p].w) };
                *(uint4*)&Bn[(p*8 + brow) * BSTRIDE + bcol] = ub;
            }
        }
        __syncthreads();
    }

    // epilogue: bias + store
    #pragma unroll
    for (int mt = 0; mt < 2; mt++) {
        #pragma unroll
        for (int nt = 0; nt < 8; nt++) {
            int c = colBase + warpN * 64 + nt * 8 + 2 * lr;
            float b0 = bias[c], b1 = bias[c + 1];
            int r0 = rowBase + warpM * 32 + mt * 16 + lq;
            float2 v0 = { acc[mt][nt][0] + b0, acc[mt][nt][1] + b1 };
            *(float2*)&C[(size_t)r0 * N + c] = v0;
            float2 v1 = { acc[mt][nt][2] + b0, acc[mt][nt][3] + b1 };
            *(float2*)&C[(size_t)(r0 + 8) * N + c] = v1;
        }
    }
}

// ---------------------------------------------------------------------------
// TF32 flash attention. Grid (16, 12, 2), 256 threads (8 warps, 4x2).
// Per block: 128 q rows, loop over 16 key tiles of 128.
// smem word offsets:
//   Qs[128][68], Ks[128][68], Vs[128][72], Ps[128][132], redA/B[128][2], mask
// ---------------------------------------------------------------------------
#define QS 0
#define KS 8704
#define VS 17408
#define PS 26624
#define RA 43520
#define RB 43776
#define MK 44032
#define ATT_SMEM_BYTES (44544 * 4)

__global__ void __launch_bounds__(256, 1) attn_tf32()
{
    extern __shared__ uint32_t sh[];
    float* redA = (float*)(sh + RA);
    float* redB = (float*)(sh + RB);
    unsigned char* mk = (unsigned char*)(sh + MK);

    const int tid = threadIdx.x;
    const int lane = tid & 31, wid = tid >> 5;
    const int lq = lane >> 2, lr = lane & 3;
    const int warpM = wid >> 1, warpN = wid & 1;
    const int qbase = blockIdx.x * 128;
    const int h = blockIdx.y, b = blockIdx.z;
    const int nbase = b * S_LEN;

    // sequence mask -> smem
    for (int i = tid; i < S_LEN; i += 256) mk[i] = g_mask[nbase + i];

    // Q tile (cvt to tf32)
    const int ldr = tid >> 4, ldc = (tid & 15) << 2;
    #pragma unroll
    for (int p = 0; p < 8; p++) {
        int r = p * 16 + ldr;
        float4 v = *(const float4*)&g_qkv[(size_t)(nbase + qbase + r) * QKV_COLS + h * DK + ldc];
        uint4 u = { f2tf(v.x), f2tf(v.y), f2tf(v.z), f2tf(v.w) };
        *(uint4*)&sh[QS + r * 68 + ldc] = u;
    }

    float o[2][4][4] = {};
    float mrow[2][2], lacc[2][2];
    #pragma unroll
    for (int mt = 0; mt < 2; mt++)
        #pragma unroll
        for (int hh = 0; hh < 2; hh++) { mrow[mt][hh] = -1e30f; lacc[mt][hh] = 0.f; }

    const float NEG = -1e9f, SC = 0.125f;

    for (int kt = 0; kt < S_LEN; kt += 128) {
        __syncthreads();  // prior PV done; Q/mask visible on first iter

        // K/V tiles
        #pragma unroll
        for (int p = 0; p < 8; p++) {
            int r = p * 16 + ldr;
            size_t base = (size_t)(nbase + kt + r) * QKV_COLS + h * DK + ldc;
            float4 kv = *(const float4*)&g_qkv[base + D_MODEL];
            uint4 uk = { f2tf(kv.x), f2tf(kv.y), f2tf(kv.z), f2tf(kv.w) };
            *(uint4*)&sh[KS + r * 68 + ldc] = uk;
            float4 vv = *(const float4*)&g_qkv[base + 2 * D_MODEL];
            uint4 uv = { f2tf(vv.x), f2tf(vv.y), f2tf(vv.z), f2tf(vv.w) };
            *(uint4*)&sh[VS + r * 72 + ldc] = uv;
        }
        __syncthreads();

        // scores = Q @ K^T  (warp tile 32 q x 64 k)
        float s[2][8][4] = {};
        #pragma unroll
        for (int ks = 0; ks < 8; ks++) {
            const int d = ks * 8;
            uint32_t af[2][4], bf[8][2];
            #pragma unroll
            for (int mt = 0; mt < 2; mt++) {
                int r = warpM * 32 + mt * 16 + lq;
                af[mt][0] = sh[QS + r * 68 + d + lr];
                af[mt][1] = sh[QS + (r + 8) * 68 + d + lr];
                af[mt][2] = sh[QS + r * 68 + d + lr + 4];
                af[mt][3] = sh[QS + (r + 8) * 68 + d + lr + 4];
            }
            #pragma unroll
            for (int nt = 0; nt < 8; nt++) {
                int n = warpN * 64 + nt * 8 + lq;
                bf[nt][0] = sh[KS + n * 68 + d + lr];
                bf[nt][1] = sh[KS + n * 68 + d + lr + 4];
            }
            #pragma unroll
            for (int mt = 0; mt < 2; mt++)
                #pragma unroll
                for (int nt = 0; nt < 8; nt++)
                    mma8(s[mt][nt], af[mt], bf[nt]);
        }

        // scale + mask
        unsigned char qm[2][2];
        #pragma unroll
        for (int mt = 0; mt < 2; mt++)
            #pragma unroll
            for (int hh = 0; hh < 2; hh++)
                qm[mt][hh] = mk[qbase + warpM * 32 + mt * 16 + lq + 8 * hh];
        #pragma unroll
        for (int nt = 0; nt < 8; nt++) {
            int col = warpN * 64 + nt * 8 + 2 * lr;
            unsigned char km0 = mk[kt + col], km1 = mk[kt + col + 1];
            #pragma unroll
            for (int mt = 0; mt < 2; mt++)
                #pragma unroll
                for (int r = 0; r < 4; r++) {
                    float v = s[mt][nt][r] * SC;
                    unsigned char kmb = (r & 1) ? km1 : km0;
                    if (kmb | qm[mt][r >> 1]) v = NEG;
                    s[mt][nt][r] = v;
                }
        }

        // row max (local 16 vals -> quad shfl -> smem cross-warpN)
        float tmax[2][2];
        #pragma unroll
        for (int mt = 0; mt < 2; mt++)
            #pragma unroll
            for (int hh = 0; hh < 2; hh++) {
                float m = -1e30f;
                #pragma unroll
                for (int nt = 0; nt < 8; nt++) {
                    m = fmaxf(m, s[mt][nt][hh * 2]);
                    m = fmaxf(m, s[mt][nt][hh * 2 + 1]);
                }
                m = fmaxf(m, __shfl_xor_sync(0xffffffffu, m, 1));
                m = fmaxf(m, __shfl_xor_sync(0xffffffffu, m, 2));
                tmax[mt][hh] = m;
            }
        if (lr == 0) {
            #pragma unroll
            for (int mt = 0; mt < 2; mt++)
                #pragma unroll
                for (int hh = 0; hh < 2; hh++)
                    redA[(warpM * 32 + mt * 16 + lq + 8 * hh) * 2 + warpN] = tmax[mt][hh];
        }
        __syncthreads();

        float mnew[2][2], alpha[2][2];
        #pragma unroll
        for (int mt = 0; mt < 2; mt++)
            #pragma unroll
            for (int hh = 0; hh < 2; hh++) {
                int row = warpM * 32 + mt * 16 + lq + 8 * hh;
                float g = fmaxf(redA[row * 2], redA[row * 2 + 1]);
                float mn = fmaxf(mrow[mt][hh], g);
                alpha[mt][hh] = __expf(mrow[mt][hh] - mn);
                mrow[mt][hh] = mn;
                mnew[mt][hh] = mn;
            }

        // exp, local sums, store P (tf32)
        float tsum[2][2] = {};
        #pragma unroll
        for (int mt = 0; mt < 2; mt++) {
            #pragma unroll
            for (int nt = 0; nt < 8; nt++) {
                #pragma unroll
                for (int r = 0; r < 4; r++) {
                    float p = __expf(s[mt][nt][r] - mnew[mt][r >> 1]);
                    s[mt][nt][r] = p;
                    tsum[mt][r >> 1] += p;
                }
                int col = warpN * 64 + nt * 8 + 2 * lr;
                #pragma unroll
                for (int hh = 0; hh < 2; hh++) {
                    int row = warpM * 32 + mt * 16 + lq + 8 * hh;
                    uint2 u = { f2tf(s[mt][nt][hh * 2]), f2tf(s[mt][nt][hh * 2 + 1]) };
                    *(uint2*)&sh[PS + row * 132 + col] = u;
                }
            }
        }
        #pragma unroll
        for (int mt = 0; mt < 2; mt++)
            #pragma unroll
            for (int hh = 0; hh < 2; hh++) {
                float t = tsum[mt][hh];
                t += __shfl_xor_sync(0xffffffffu, t, 1);
                t += __shfl_xor_sync(0xffffffffu, t, 2);
                tsum[mt][hh] = t;
            }
        if (lr == 0) {
            #pragma unroll
            for (int mt = 0; mt < 2; mt++)
                #pragma unroll
                for (int hh = 0; hh < 2; hh++)
                    redB[(warpM * 32 + mt * 16 + lq + 8 * hh) * 2 + warpN] = tsum[mt][hh];
        }
        __syncthreads();

        #pragma unroll
        for (int mt = 0; mt < 2; mt++)
            #pragma unroll
            for (int hh = 0; hh < 2; hh++) {
                int row = warpM * 32 + mt * 16 + lq + 8 * hh;
                float ls = redB[row * 2] + redB[row * 2 + 1];
                lacc[mt][hh] = lacc[mt][hh] * alpha[mt][hh] + ls;
            }
        // rescale O
        #pragma unroll
        for (int mt = 0; mt < 2; mt++)
            #pragma unroll
            for (int nt2 = 0; nt2 < 4; nt2++)
                #pragma unroll
                for (int r = 0; r < 4; r++)
                    o[mt][nt2][r] *= alpha[mt][r >> 1];

        // PV: O += P @ V  (warp tile 32 q x 32 d, K-dim 128 keys)
        #pragma unroll
        for (int kk = 0; kk < 16; kk++) {
            const int k = kk * 8;
            uint32_t af[2][4], bf[4][2];
            #pragma unroll
            for (int mt = 0; mt < 2; mt++) {
                int r = warpM * 32 + mt * 16 + lq;
                af[mt][0] = sh[PS + r * 132 + k + lr];
                af[mt][1] = sh[PS + (r + 8) * 132 + k + lr];
                af[mt][2] = sh[PS + r * 132 + k + lr + 4];
                af[mt][3] = sh[PS + (r + 8) * 132 + k + lr + 4];
            }
            #pragma unroll
            for (int nt2 = 0; nt2 < 4; nt2++) {
                int n = warpN * 32 + nt2 * 8 + lq;
                bf[nt2][0] = sh[VS + (k + lr) * 72 + n];
                bf[nt2][1] = sh[VS + (k + lr + 4) * 72 + n];
            }
            #pragma unroll
            for (int mt = 0; mt < 2; mt++)
                #pragma unroll
                for (int nt2 = 0; nt2 < 4; nt2++)
                    mma8(o[mt][nt2], af[mt], bf[nt2]);
        }
    }

    // normalize + write out as [B, S, H*dk]
    #pragma unroll
    for (int mt = 0; mt < 2; mt++) {
        float inv0 = 1.0f / lacc[mt][0];
        float inv1 = 1.0f / lacc[mt][1];
        #pragma unroll
        for (int nt2 = 0; nt2 < 4; nt2++) {
            int col = warpN * 32 + nt2 * 8 + 2 * lr;
            int row0 = warpM * 32 + mt * 16 + lq;
            float2 v0 = { o[mt][nt2][0] * inv0, o[mt][nt2][1] * inv0 };
            *(float2*)&g_attn[(size_t)(nbase + qbase + row0) * D_MODEL + h * DK + col] = v0;
            float2 v1 = { o[mt][nt2][2] * inv1, o[mt][nt2][3] * inv1 };
            *(float2*)&g_attn[(size_t)(nbase + qbase + row0 + 8) * D_MODEL + h * DK + col] = v1;
        }
    }
}

// ---------------------------------------------------------------------------
// Launch
// ---------------------------------------------------------------------------
extern "C" void kernel_launch(void* const* d_in, const int* in_sizes, int n_in,
                              void* d_out, int out_size)
{
    const float*         x    = (const float*)d_in[0];
    const unsigned char* mask = (const unsigned char*)d_in[1];
    const float*         Wqkv = (const float*)d_in[2];
    const float*         bqkv = (const float*)d_in[3];
    const float*         Wout = (const float*)d_in[4];
    const float*         bout = (const float*)d_in[5];
    float*               out  = (float*)d_out;

    cudaFuncSetAttribute(gemm_tf32_bias,
                         cudaFuncAttributeMaxDynamicSharedMemorySize, GEMM_SMEM_BYTES);
    cudaFuncSetAttribute(attn_tf32,
                         cudaFuncAttributeMaxDynamicSharedMemorySize, ATT_SMEM_BYTES);

    void* qkv_ptr  = nullptr;
    void* attn_ptr = nullptr;
    cudaGetSymbolAddress(&qkv_ptr, g_qkv);
    cudaGetSymbolAddress(&attn_ptr, g_attn);

    prep_mask_kernel<<<1, 256>>>(mask);

    // QKV projection: [4096,768] @ [768,2304] + bias
    gemm_tf32_bias<<<dim3(QKV_COLS / 128, NTOK / 128), 256, GEMM_SMEM_BYTES>>>(
        x, Wqkv, bqkv, (float*)qkv_ptr, NTOK, QKV_COLS, D_MODEL);

    // Masked multi-head attention
    attn_tf32<<<dim3(S_LEN / 128, N_HEAD, BATCH), 256, ATT_SMEM_BYTES>>>();

    // Output projection: [4096,768] @ [768,768] + bias
    gemm_tf32_bias<<<dim3(D_MODEL / 128, NTOK / 128), 256, GEMM_SMEM_BYTES>>>(
        (const float*)attn_ptr, Wout, bout, out, NTOK, D_MODEL, D_MODEL);
}

// round 7
// speedup vs baseline: 3.3356x; 1.1222x over previous
#include <cuda_runtime.h>
#include <cstdint>

#define S_LEN   2048
#define D_MODEL 768
#define N_HEAD  12
#define DK      64
#define BATCH   2
#define NTOK    4096
#define QKV_COLS 2304

__device__ float g_qkv[NTOK * QKV_COLS];    // tf32-canonical after QKV gemm
__device__ float g_attn[NTOK * D_MODEL];    // tf32-canonical after attention
__device__ float g_xr[NTOK * D_MODEL];      // tf32-rounded x
__device__ float g_wqkvr[D_MODEL * QKV_COLS];
__device__ float g_woutr[D_MODEL * D_MODEL];
__device__ unsigned char g_mask[NTOK];

// ---------------------------------------------------------------------------
// helpers
// ---------------------------------------------------------------------------
__device__ __forceinline__ uint32_t smem_u32(const void* p) {
    uint32_t a;
    asm("{ .reg .u64 t; cvta.to.shared.u64 t, %1; cvt.u32.u64 %0, t; }"
        : "=r"(a) : "l"(p));
    return a;
}
__device__ __forceinline__ void cpa16(uint32_t dst, const void* src) {
    asm volatile("cp.async.cg.shared.global [%0], [%1], 16;" :: "r"(dst), "l"(src));
}
__device__ __forceinline__ void cpa_commit() {
    asm volatile("cp.async.commit_group;");
}
template <int N>
__device__ __forceinline__ void cpa_wait() {
    asm volatile("cp.async.wait_group %0;" :: "n"(N));
}
__device__ __forceinline__ uint32_t f2tf(float f) {
    uint32_t u;
    asm("cvt.rna.tf32.f32 %0, %1;" : "=r"(u) : "f"(f));
    return u;
}
// operands are canonical tf32 encodings (low 13 bits zero)
__device__ __forceinline__ void mma8(float* c, const uint32_t* a, const uint32_t* b) {
    asm("mma.sync.aligned.m16n8k8.row.col.f32.tf32.tf32.f32 "
        "{%0,%1,%2,%3}, {%4,%5,%6,%7}, {%8,%9}, {%0,%1,%2,%3};"
        : "+f"(c[0]), "+f"(c[1]), "+f"(c[2]), "+f"(c[3])
        : "r"(a[0]), "r"(a[1]), "r"(a[2]), "r"(a[3]), "r"(b[0]), "r"(b[1]));
}

// ---------------------------------------------------------------------------
// Pre-round inputs to canonical tf32 encodings (stored as fp32 bits)
// ---------------------------------------------------------------------------
__global__ void preround_kernel(const float* __restrict__ x,
                                const float* __restrict__ wqkv,
                                const float* __restrict__ wout)
{
    const int stride = gridDim.x * blockDim.x;
    const int i0 = blockIdx.x * blockDim.x + threadIdx.x;
    for (int j = i0; j < NTOK * D_MODEL / 4; j += stride) {
        float4 v = ((const float4*)x)[j];
        uint4 u = { f2tf(v.x), f2tf(v.y), f2tf(v.z), f2tf(v.w) };
        ((uint4*)g_xr)[j] = u;
    }
    for (int j = i0; j < D_MODEL * QKV_COLS / 4; j += stride) {
        float4 v = ((const float4*)wqkv)[j];
        uint4 u = { f2tf(v.x), f2tf(v.y), f2tf(v.z), f2tf(v.w) };
        ((uint4*)g_wqkvr)[j] = u;
    }
    for (int j = i0; j < D_MODEL * D_MODEL / 4; j += stride) {
        float4 v = ((const float4*)wout)[j];
        uint4 u = { f2tf(v.x), f2tf(v.y), f2tf(v.z), f2tf(v.w) };
        ((uint4*)g_woutr)[j] = u;
    }
}

// ---------------------------------------------------------------------------
// Mask canonicalization (1-byte vs 4-byte bool layouts)
// ---------------------------------------------------------------------------
__global__ void prep_mask_kernel(const unsigned char* __restrict__ m) {
    __shared__ int flags[2];
    if (threadIdx.x < 2) flags[threadIdx.x] = 0;
    __syncthreads();
    for (int i = threadIdx.x; i < NTOK; i += blockDim.x) {
        unsigned char v = m[i];
        if (v) {
            atomicOr(&flags[0], 1);
            if ((i & 3) == 1) atomicOr(&flags[1], 1);
        }
    }
    __syncthreads();
    int has_any = flags[0], one_byte = flags[1];
    for (int i = threadIdx.x; i < NTOK; i += blockDim.x) {
        unsigned char v;
        if (!has_any)      v = 0;
        else if (one_byte) v = m[i] ? 1 : 0;
        else               v = (m[4*i] | m[4*i+1] | m[4*i+2] | m[4*i+3]) ? 1 : 0;
        g_mask[i] = v;
    }
}

// ---------------------------------------------------------------------------
// TF32 GEMM with bias: C[M,N] = A[M,K] @ B[K,N] + bias
// 128x128x32 tiles, 256 threads (8 warps 4x2), warp tile 32x64.
// 3-stage cp.async pipeline, 2 CTAs/SM. Inputs tf32-canonical.
// ---------------------------------------------------------------------------
#define GBK 32
#define ASTRIDE 36
#define BSTRIDE 136
#define AWORDS (128 * ASTRIDE)   // 4608
#define BWORDS (GBK * BSTRIDE)   // 4352
#define STWORDS (AWORDS + BWORDS)
#define GSTAGES 3
#define GEMM_SMEM_BYTES (GSTAGES * STWORDS * 4)

template <bool ROUND_OUT>
__global__ void __launch_bounds__(256, 2)
gemm_tf32_bias(const float* __restrict__ A, const float* __restrict__ B,
               const float* __restrict__ bias, float* __restrict__ C,
               int M, int N, int K)
{
    extern __shared__ uint32_t sh[];
    const uint32_t sbase = smem_u32(sh);

    const int tid = threadIdx.x;
    const int lane = tid & 31, wid = tid >> 5;
    const int lq = lane >> 2, lr = lane & 3;
    const int warpM = wid >> 1, warpN = wid & 1;
    const int rowBase = blockIdx.y * 128, colBase = blockIdx.x * 128;

    float acc[2][8][4] = {};

    auto issue_stage = [&](int buf, int k0) {
        uint32_t abase = sbase + (uint32_t)(buf * STWORDS) * 4;
        uint32_t bbase = abase + AWORDS * 4;
        #pragma unroll
        for (int i = 0; i < 4; i++) {
            int c = tid + i * 256;
            int r = c >> 3, kc = (c & 7) << 2;
            cpa16(abase + (uint32_t)(r * ASTRIDE + kc) * 4,
                  &A[(size_t)(rowBase + r) * K + k0 + kc]);
        }
        #pragma unroll
        for (int i = 0; i < 4; i++) {
            int c = tid + i * 256;
            int r = c >> 5, nc = (c & 31) << 2;
            cpa16(bbase + (uint32_t)(r * BSTRIDE + nc) * 4,
                  &B[(size_t)(k0 + r) * N + colBase + nc]);
        }
    };

    const int T = K / GBK;
    issue_stage(0, 0);  cpa_commit();
    issue_stage(1, GBK); cpa_commit();
    cpa_wait<1>();
    __syncthreads();

    for (int t = 0; t < T; t++) {
        if (t + 2 < T) issue_stage((t + 2) % GSTAGES, (t + 2) * GBK);
        cpa_commit();

        const uint32_t* Ab = sh + (t % GSTAGES) * STWORDS;
        const uint32_t* Bb = Ab + AWORDS;

        #pragma unroll
        for (int ks = 0; ks < 4; ks++) {
            const int k = ks * 8;
            uint32_t af[2][4], bf[8][2];
            #pragma unroll
            for (int mt = 0; mt < 2; mt++) {
                int r = warpM * 32 + mt * 16 + lq;
                af[mt][0] = Ab[r * ASTRIDE + k + lr];
                af[mt][1] = Ab[(r + 8) * ASTRIDE + k + lr];
                af[mt][2] = Ab[r * ASTRIDE + k + lr + 4];
                af[mt][3] = Ab[(r + 8) * ASTRIDE + k + lr + 4];
            }
            #pragma unroll
            for (int nt = 0; nt < 8; nt++) {
                int n = warpN * 64 + nt * 8 + lq;
                bf[nt][0] = Bb[(k + lr) * BSTRIDE + n];
                bf[nt][1] = Bb[(k + lr + 4) * BSTRIDE + n];
            }
            #pragma unroll
            for (int mt = 0; mt < 2; mt++)
                #pragma unroll
                for (int nt = 0; nt < 8; nt++)
                    mma8(acc[mt][nt], af[mt], bf[nt]);
        }

        cpa_wait<1>();
        __syncthreads();
    }

    // epilogue: bias + store (optionally tf32-rounded for chained consumers)
    #pragma unroll
    for (int mt = 0; mt < 2; mt++) {
        #pragma unroll
        for (int nt = 0; nt < 8; nt++) {
            int c = colBase + warpN * 64 + nt * 8 + 2 * lr;
            float b0 = bias[c], b1 = bias[c + 1];
            int r0 = rowBase + warpM * 32 + mt * 16 + lq;
            float v00 = acc[mt][nt][0] + b0, v01 = acc[mt][nt][1] + b1;
            float v10 = acc[mt][nt][2] + b0, v11 = acc[mt][nt][3] + b1;
            if (ROUND_OUT) {
                v00 = __uint_as_float(f2tf(v00)); v01 = __uint_as_float(f2tf(v01));
                v10 = __uint_as_float(f2tf(v10)); v11 = __uint_as_float(f2tf(v11));
            }
            float2 w0 = { v00, v01 };
            *(float2*)&C[(size_t)r0 * N + c] = w0;
            float2 w1 = { v10, v11 };
            *(float2*)&C[(size_t)(r0 + 8) * N + c] = w1;
        }
    }
}

// ---------------------------------------------------------------------------
// TF32 flash attention. Grid (16, 12, 2), 256 threads (8 warps 4x2).
// 128 q rows / block, 16 key tiles of 128.
// K double-buffered (prefetch next tile), V single-buffered (loaded at tile
// start, waited just before PV). P stride 132 (full 128x128 tile, no overlap).
// smem word layout (53248 words = 212992 bytes):
//   Qs[128][68]      @0      .. 8704
//   Ks[2][128][68]   @8704   .. 26112
//   Vs[128][72]      @26112  .. 35328
//   Ps[128][132]     @35328  .. 52224
//   redA[128][2]     @52224  .. 52480
//   redB[128][2]     @52480  .. 52736
//   mask (2048 B)    @52736  .. 53248
// ---------------------------------------------------------------------------
#define QS 0
#define KSO 8704
#define KBUF 8704
#define VS 26112
#define PS 35328
#define PSTRIDE 132
#define RA 52224
#define RB 52480
#define MK 52736
#define ATT_SMEM_BYTES (53248 * 4)

__global__ void __launch_bounds__(256, 1) attn_tf32()
{
    extern __shared__ uint32_t sh[];
    const uint32_t sbase = smem_u32(sh);
    float* redA = (float*)(sh + RA);
    float* redB = (float*)(sh + RB);
    unsigned char* mk = (unsigned char*)(sh + MK);

    const int tid = threadIdx.x;
    const int lane = tid & 31, wid = tid >> 5;
    const int lq = lane >> 2, lr = lane & 3;
    const int warpM = wid >> 1, warpN = wid & 1;
    const int qbase = blockIdx.x * 128;
    const int h = blockIdx.y, b = blockIdx.z;
    const int nbase = b * S_LEN;

    const float* qkv = g_qkv;

    auto issue_k = [&](int buf, int kt) {
        uint32_t kbase = sbase + (uint32_t)(KSO + buf * KBUF) * 4;
        #pragma unroll
        for (int i = 0; i < 8; i++) {
            int c = tid + i * 256;
            int r = c >> 4, col = (c & 15) << 2;
            size_t src = (size_t)(nbase + kt + r) * QKV_COLS + h * DK + col;
            cpa16(kbase + (uint32_t)(r * 68 + col) * 4, &qkv[src + D_MODEL]);
        }
    };
    auto issue_v = [&](int kt) {
        uint32_t vbase = sbase + (uint32_t)VS * 4;
        #pragma unroll
        for (int i = 0; i < 8; i++) {
            int c = tid + i * 256;
            int r = c >> 4, col = (c & 15) << 2;
            size_t src = (size_t)(nbase + kt + r) * QKV_COLS + h * DK + col;
            cpa16(vbase + (uint32_t)(r * 72 + col) * 4, &qkv[src + 2 * D_MODEL]);
        }
    };

    // mask -> smem (plain stores)
    for (int i = tid; i < S_LEN; i += 256) mk[i] = g_mask[nbase + i];

    // Q + K(0) as the first cp.async group
    #pragma unroll
    for (int i = 0; i < 8; i++) {
        int c = tid + i * 256;
        int r = c >> 4, col = (c & 15) << 2;
        cpa16(sbase + (uint32_t)(QS + r * 68 + col) * 4,
              &qkv[(size_t)(nbase + qbase + r) * QKV_COLS + h * DK + col]);
    }
    issue_k(0, 0);
    cpa_commit();
    __syncthreads();          // mask visible (cp.async not yet required)

    float o[2][4][4] = {};
    float mrow[2][2], lacc[2][2];
    #pragma unroll
    for (int mt = 0; mt < 2; mt++)
        #pragma unroll
        for (int hh = 0; hh < 2; hh++) { mrow[mt][hh] = -1e30f; lacc[mt][hh] = 0.f; }

    const float NEG = -1e9f, SC = 0.125f;

    unsigned char qm[2][2];
    #pragma unroll
    for (int mt = 0; mt < 2; mt++)
        #pragma unroll
        for (int hh = 0; hh < 2; hh++)
            qm[mt][hh] = mk[qbase + warpM * 32 + mt * 16 + lq + 8 * hh];

    const int NT = S_LEN / 128;
    for (int ti = 0; ti < NT; ti++) {
        const int kt = ti * 128;
        const int cur = ti & 1;

        // group 2ti+1: V(ti) into the single V buffer (prior PV reads done
        // behind the end-of-tile barrier)
        issue_v(kt);
        cpa_commit();
        // group 2ti+2: K(ti+1) prefetch into the other K buffer
        if (ti + 1 < NT) issue_k(cur ^ 1, kt + 128);
        cpa_commit();

        // need Q + K(ti) (committed 2 groups back): <=2 pending allowed
        cpa_wait<2>();
        __syncthreads();      // (A) K(ti)/Q visible to all warps

        const uint32_t* Kb = sh + KSO + cur * KBUF;

        // scores = Q @ K^T (warp tile 32q x 64k)
        float s[2][8][4] = {};
        #pragma unroll
        for (int ks = 0; ks < 8; ks++) {
            const int d = ks * 8;
            uint32_t af[2][4], bf[8][2];
            #pragma unroll
            for (int mt = 0; mt < 2; mt++) {
                int r = warpM * 32 + mt * 16 + lq;
                af[mt][0] = sh[QS + r * 68 + d + lr];
                af[mt][1] = sh[QS + (r + 8) * 68 + d + lr];
                af[mt][2] = sh[QS + r * 68 + d + lr + 4];
                af[mt][3] = sh[QS + (r + 8) * 68 + d + lr + 4];
            }
            #pragma unroll
            for (int nt = 0; nt < 8; nt++) {
                int n = warpN * 64 + nt * 8 + lq;
                bf[nt][0] = Kb[n * 68 + d + lr];
                bf[nt][1] = Kb[n * 68 + d + lr + 4];
            }
            #pragma unroll
            for (int mt = 0; mt < 2; mt++)
                #pragma unroll
                for (int nt = 0; nt < 8; nt++)
                    mma8(s[mt][nt], af[mt], bf[nt]);
        }

        // scale + mask
        #pragma unroll
        for (int nt = 0; nt < 8; nt++) {
            int col = warpN * 64 + nt * 8 + 2 * lr;
            unsigned char km0 = mk[kt + col], km1 = mk[kt + col + 1];
            #pragma unroll
            for (int mt = 0; mt < 2; mt++)
                #pragma unroll
                for (int r = 0; r < 4; r++) {
                    float v = s[mt][nt][r] * SC;
                    unsigned char kmb = (r & 1) ? km1 : km0;
                    if (kmb | qm[mt][r >> 1]) v = NEG;
                    s[mt][nt][r] = v;
                }
        }

        // row max: local -> quad shfl -> smem cross-warpN
        float tmax[2][2];
        #pragma unroll
        for (int mt = 0; mt < 2; mt++)
            #pragma unroll
            for (int hh = 0; hh < 2; hh++) {
                float m = -1e30f;
                #pragma unroll
                for (int nt = 0; nt < 8; nt++) {
                    m = fmaxf(m, s[mt][nt][hh * 2]);
                    m = fmaxf(m, s[mt][nt][hh * 2 + 1]);
                }
                m = fmaxf(m, __shfl_xor_sync(0xffffffffu, m, 1));
                m = fmaxf(m, __shfl_xor_sync(0xffffffffu, m, 2));
                tmax[mt][hh] = m;
            }
        if (lr == 0) {
            #pragma unroll
            for (int mt = 0; mt < 2; mt++)
                #pragma unroll
                for (int hh = 0; hh < 2; hh++)
                    redA[(warpM * 32 + mt * 16 + lq + 8 * hh) * 2 + warpN] = tmax[mt][hh];
        }
        __syncthreads();      // (1) redA ready; all warps past old-P reads

        float mnew[2][2], alpha[2][2];
        #pragma unroll
        for (int mt = 0; mt < 2; mt++)
            #pragma unroll
            for (int hh = 0; hh < 2; hh++) {
                int row = warpM * 32 + mt * 16 + lq + 8 * hh;
                float g = fmaxf(redA[row * 2], redA[row * 2 + 1]);
                float mn = fmaxf(mrow[mt][hh], g);
                alpha[mt][hh] = __expf(mrow[mt][hh] - mn);
                mrow[mt][hh] = mn;
                mnew[mt][hh] = mn;
            }

        // exp, local sums, store P (canonical tf32, stride 132: no overlap)
        float tsum[2][2] = {};
        #pragma unroll
        for (int mt = 0; mt < 2; mt++) {
            #pragma unroll
            for (int nt = 0; nt < 8; nt++) {
                #pragma unroll
                for (int r = 0; r < 4; r++) {
                    float p = __expf(s[mt][nt][r] - mnew[mt][r >> 1]);
                    s[mt][nt][r] = p;
                    tsum[mt][r >> 1] += p;
                }
                int col = warpN * 64 + nt * 8 + 2 * lr;
                #pragma unroll
                for (int hh = 0; hh < 2; hh++) {
                    int row = warpM * 32 + mt * 16 + lq + 8 * hh;
                    uint2 u = { f2tf(s[mt][nt][hh * 2]),
                                f2tf(s[mt][nt][hh * 2 + 1]) };
                    *(uint2*)&sh[PS + row * PSTRIDE + col] = u;
                }
            }
        }
        #pragma unroll
        for (int mt = 0; mt < 2; mt++)
            #pragma unroll
            for (int hh = 0; hh < 2; hh++) {
                float t = tsum[mt][hh];
                t += __shfl_xor_sync(0xffffffffu, t, 1);
                t += __shfl_xor_sync(0xffffffffu, t, 2);
                tsum[mt][hh] = t;
            }
        if (lr == 0) {
            #pragma unroll
            for (int mt = 0; mt < 2; mt++)
                #pragma unroll
                for (int hh = 0; hh < 2; hh++)
                    redB[(warpM * 32 + mt * 16 + lq + 8 * hh) * 2 + warpN] = tsum[mt][hh];
        }
        __syncthreads();      // (2) P + redB visible

        #pragma unroll
        for (int mt = 0; mt < 2; mt++)
            #pragma unroll
            for (int hh = 0; hh < 2; hh++) {
                int row = warpM * 32 + mt * 16 + lq + 8 * hh;
                float ls = redB[row * 2] + redB[row * 2 + 1];
                lacc[mt][hh] = lacc[mt][hh] * alpha[mt][hh] + ls;
            }
        #pragma unroll
        for (int mt = 0; mt < 2; mt++)
            #pragma unroll
            for (int nt2 = 0; nt2 < 4; nt2++)
                #pragma unroll
                for (int r = 0; r < 4; r++)
                    o[mt][nt2][r] *= alpha[mt][r >> 1];

        // V(ti) must be resident: <=1 pending (K(ti+1) may still fly)
        cpa_wait<1>();
        __syncthreads();      // (B) V visible to all warps

        // PV: O += P @ V (warp tile 32q x 32d over 128 keys)
        #pragma unroll
        for (int kk = 0; kk < 16; kk++) {
            const int k = kk * 8;
            uint32_t af[2][4], bf[4][2];
            #pragma unroll
            for (int mt = 0; mt < 2; mt++) {
                int r = warpM * 32 + mt * 16 + lq;
                af[mt][0] = sh[PS + r * PSTRIDE + k + lr];
                af[mt][1] = sh[PS + (r + 8) * PSTRIDE + k + lr];
                af[mt][2] = sh[PS + r * PSTRIDE + k + lr + 4];
                af[mt][3] = sh[PS + (r + 8) * PSTRIDE + k + lr + 4];
            }
            #pragma unroll
            for (int nt2 = 0; nt2 < 4; nt2++) {
                int n = warpN * 32 + nt2 * 8 + lq;
                bf[nt2][0] = sh[VS + (k + lr) * 72 + n];
                bf[nt2][1] = sh[VS + (k + lr + 4) * 72 + n];
            }
            #pragma unroll
            for (int mt = 0; mt < 2; mt++)
                #pragma unroll
                for (int nt2 = 0; nt2 < 4; nt2++)
                    mma8(o[mt][nt2], af[mt], bf[nt2]);
        }

        __syncthreads();      // (3) PV reads done before next tile's V/P writes
    }

    // normalize + write out (tf32-canonical for the out-projection GEMM)
    #pragma unroll
    for (int mt = 0; mt < 2; mt++) {
        float inv0 = 1.0f / lacc[mt][0];
        float inv1 = 1.0f / lacc[mt][1];
        #pragma unroll
        for (int nt2 = 0; nt2 < 4; nt2++) {
            int col = warpN * 32 + nt2 * 8 + 2 * lr;
            int row0 = warpM * 32 + mt * 16 + lq;
            float2 v0 = { __uint_as_float(f2tf(o[mt][nt2][0] * inv0)),
                          __uint_as_float(f2tf(o[mt][nt2][1] * inv0)) };
            *(float2*)&g_attn[(size_t)(nbase + qbase + row0) * D_MODEL + h * DK + col] = v0;
            float2 v1 = { __uint_as_float(f2tf(o[mt][nt2][2] * inv1)),
                          __uint_as_float(f2tf(o[mt][nt2][3] * inv1)) };
            *(float2*)&g_attn[(size_t)(nbase + qbase + row0 + 8) * D_MODEL + h * DK + col] = v1;
        }
    }
}

// ---------------------------------------------------------------------------
// Launch
// ---------------------------------------------------------------------------
extern "C" void kernel_launch(void* const* d_in, const int* in_sizes, int n_in,
                              void* d_out, int out_size)
{
    const float*         x    = (const float*)d_in[0];
    const unsigned char* mask = (const unsigned char*)d_in[1];
    const float*         Wqkv = (const float*)d_in[2];
    const float*         bqkv = (const float*)d_in[3];
    const float*         Wout = (const float*)d_in[4];
    const float*         bout = (const float*)d_in[5];
    float*               out  = (float*)d_out;

    cudaFuncSetAttribute(gemm_tf32_bias<true>,
                         cudaFuncAttributeMaxDynamicSharedMemorySize, GEMM_SMEM_BYTES);
    cudaFuncSetAttribute(gemm_tf32_bias<false>,
                         cudaFuncAttributeMaxDynamicSharedMemorySize, GEMM_SMEM_BYTES);
    cudaFuncSetAttribute(attn_tf32,
                         cudaFuncAttributeMaxDynamicSharedMemorySize, ATT_SMEM_BYTES);

    void* qkv_ptr  = nullptr;
    void* attn_ptr = nullptr;
    void* xr_ptr   = nullptr;
    void* wqkvr_ptr = nullptr;
    void* woutr_ptr = nullptr;
    cudaGetSymbolAddress(&qkv_ptr,  g_qkv);
    cudaGetSymbolAddress(&attn_ptr, g_attn);
    cudaGetSymbolAddress(&xr_ptr,   g_xr);
    cudaGetSymbolAddress(&wqkvr_ptr, g_wqkvr);
    cudaGetSymbolAddress(&woutr_ptr, g_woutr);

    preround_kernel<<<1024, 256>>>(x, Wqkv, Wout);
    prep_mask_kernel<<<1, 256>>>(mask);

    // QKV projection: [4096,768] @ [768,2304] + bias  -> tf32-rounded output
    gemm_tf32_bias<true><<<dim3(QKV_COLS / 128, NTOK / 128), 256, GEMM_SMEM_BYTES>>>(
        (const float*)xr_ptr, (const float*)wqkvr_ptr, bqkv, (float*)qkv_ptr,
        NTOK, QKV_COLS, D_MODEL);

    // Masked multi-head attention
    attn_tf32<<<dim3(S_LEN / 128, N_HEAD, BATCH), 256, ATT_SMEM_BYTES>>>();

    // Output projection: [4096,768] @ [768,768] + bias  -> plain fp32 output
    gemm_tf32_bias<false><<<dim3(D_MODEL / 128, NTOK / 128), 256, GEMM_SMEM_BYTES>>>(
        (const float*)attn_ptr, (const float*)woutr_ptr, bout, out,
        NTOK, D_MODEL, D_MODEL);
}